// round 1
// baseline (speedup 1.0000x reference)
#include <cuda_runtime.h>
#include <math.h>

#define EPSV 1e-5f
#define BB 2
#define CC 256
#define C8 32
#define NP 4096          // 16*16*16 positions
#define PADN 5832        // 18*18*18
#define KCONV (CC*27)    // 6912

// ---------------- scratch (static __device__, no allocation) ----------------
__device__ float g_pad[BB*CC*PADN];      // padded conv input (reused conv1/conv2)
__device__ float g_y[BB*CC*NP];          // conv output (reused)
__device__ float g_out[BB*CC*NP];        // residual branch output "out"
__device__ float g_q[BB*C8*NP];
__device__ float g_k[BB*C8*NP];
__device__ float g_v[BB*CC*NP];
__device__ float g_attn[(size_t)BB*NP*NP];   // 134 MB
__device__ float g_mean[BB*CC];
__device__ float g_rstd[BB*CC];

// padded-offset per conv tap: (dx*324 + dy*18 + dz), dx,dy,dz in {-1,0,1}, tap = (dx+1)*9+(dy+1)*3+(dz+1)
__constant__ int c_doff[27] = {
  -343,-342,-341,-325,-324,-323,-307,-306,-305,
   -19, -18, -17,  -1,   0,   1,  17,  18,  19,
   305, 306, 307, 323, 324, 325, 341, 342, 343};

// ---------------- pad kernel: mode 0: copy x -> g_pad ; mode 1: instnorm+relu(g_y) -> g_pad
__global__ void pad_kernel(const float* __restrict__ x, int mode) {
    int bc = blockIdx.x;             // 0..511
    const float* src = (mode == 0) ? (x + bc * NP) : (g_y + bc * NP);
    float m = 0.f, r = 1.f;
    if (mode == 1) { m = g_mean[bc]; r = g_rstd[bc]; }
    float* dst = g_pad + bc * PADN;
    for (int i = threadIdx.x; i < PADN; i += blockDim.x) {
        int zp = i % 18; int t = i / 18; int yp = t % 18; int xp = t / 18;
        float v = 0.f;
        if (xp >= 1 && xp <= 16 && yp >= 1 && yp <= 16 && zp >= 1 && zp <= 16) {
            v = src[(xp - 1) * 256 + (yp - 1) * 16 + (zp - 1)];
            if (mode == 1) { v = (v - m) * r; v = v > 0.f ? v : 0.f; }
        }
        dst[i] = v;
    }
}

// ---------------- per-(b,c) mean/rstd over 4096 elements of g_y ----------------
__global__ void stats_kernel() {
    int bc = blockIdx.x;
    const float* src = g_y + bc * NP;
    float s = 0.f, ss = 0.f;
    for (int i = threadIdx.x; i < NP; i += 256) {
        float v = src[i]; s += v; ss += v * v;
    }
    #pragma unroll
    for (int o = 16; o; o >>= 1) {
        s  += __shfl_down_sync(0xffffffffu, s, o);
        ss += __shfl_down_sync(0xffffffffu, ss, o);
    }
    __shared__ float sh_s[8], sh_ss[8];
    int w = threadIdx.x >> 5, l = threadIdx.x & 31;
    if (l == 0) { sh_s[w] = s; sh_ss[w] = ss; }
    __syncthreads();
    if (threadIdx.x == 0) {
        float S = 0.f, SS = 0.f;
        #pragma unroll
        for (int i = 0; i < 8; i++) { S += sh_s[i]; SS += sh_ss[i]; }
        float m = S * (1.0f / NP);
        float var = SS * (1.0f / NP) - m * m;
        g_mean[bc] = m;
        g_rstd[bc] = rsqrtf(var + EPSV);
    }
}

// ---------------- out = x + instnorm(g_y) ----------------
__global__ void norm_add_kernel(const float* __restrict__ x) {
    int idx = blockIdx.x * 256 + threadIdx.x;     // 0 .. 2M-1
    int bc = idx >> 12;
    float m = g_mean[bc], r = g_rstd[bc];
    g_out[idx] = x[idx] + (g_y[idx] - m) * r;
}

// ---------------- conv as implicit GEMM: g_y[b,co,p] = sum_k w[co,k]*g_pad[b,cin,p+off] + bias
// tile 128(co) x 128(p), BK=8, 256 threads, 8x8 reg tile
__global__ __launch_bounds__(256) void conv_gemm(const float* __restrict__ w,
                                                 const float* __restrict__ bias) {
    __shared__ float As[8][128];
    __shared__ float Bs[8][128];
    int tid = threadIdx.x;
    int b   = blockIdx.z;
    int co0 = blockIdx.y * 128;
    int p0  = blockIdx.x * 128;
    const float* xb = g_pad + b * CC * PADN;

    // B-loader: row kk_row (0..7), 4 consecutive p
    int kk_row = tid >> 5;
    int pl = (tid & 31) * 4;
    int ppos[4];
    #pragma unroll
    for (int j = 0; j < 4; j++) {
        int p = p0 + pl + j;
        int pz = p & 15, py = (p >> 4) & 15, px = p >> 8;
        ppos[j] = (px + 1) * 324 + (py + 1) * 18 + (pz + 1);
    }
    int cin = 0, tap = kk_row;

    // A-loader: row arow, 4 consecutive k
    int arow = tid >> 1;
    int acol = (tid & 1) * 4;
    const float* aptr = w + (size_t)(co0 + arow) * KCONV + acol;

    int ty = tid >> 4, tx = tid & 15;
    float acc[8][8];
    #pragma unroll
    for (int i = 0; i < 8; i++)
        #pragma unroll
        for (int j = 0; j < 8; j++) acc[i][j] = 0.f;

    for (int it = 0; it < KCONV / 8; ++it) {
        float4 av = *(const float4*)(aptr + it * 8);
        const float* src = xb + cin * PADN + c_doff[tap];
        float b0 = src[ppos[0]];
        float b1 = src[ppos[1]];
        float b2 = src[ppos[2]];
        float b3 = src[ppos[3]];
        __syncthreads();
        As[acol + 0][arow] = av.x;
        As[acol + 1][arow] = av.y;
        As[acol + 2][arow] = av.z;
        As[acol + 3][arow] = av.w;
        *(float4*)&Bs[kk_row][pl] = make_float4(b0, b1, b2, b3);
        __syncthreads();
        #pragma unroll
        for (int kk = 0; kk < 8; kk++) {
            float a[8], bv[8];
            float4 t0 = *(const float4*)&As[kk][ty * 8];
            float4 t1 = *(const float4*)&As[kk][ty * 8 + 4];
            a[0]=t0.x; a[1]=t0.y; a[2]=t0.z; a[3]=t0.w;
            a[4]=t1.x; a[5]=t1.y; a[6]=t1.z; a[7]=t1.w;
            float4 u0 = *(const float4*)&Bs[kk][tx * 8];
            float4 u1 = *(const float4*)&Bs[kk][tx * 8 + 4];
            bv[0]=u0.x; bv[1]=u0.y; bv[2]=u0.z; bv[3]=u0.w;
            bv[4]=u1.x; bv[5]=u1.y; bv[6]=u1.z; bv[7]=u1.w;
            #pragma unroll
            for (int i = 0; i < 8; i++)
                #pragma unroll
                for (int j = 0; j < 8; j++)
                    acc[i][j] += a[i] * bv[j];
        }
        tap += 8;
        if (tap >= 27) { tap -= 27; cin++; }
    }
    #pragma unroll
    for (int i = 0; i < 8; i++) {
        int co = co0 + ty * 8 + i;
        float bsv = bias[co];
        float* dst = g_y + ((b * CC + co) * NP) + p0 + tx * 8;
        *(float4*)dst       = make_float4(acc[i][0]+bsv, acc[i][1]+bsv, acc[i][2]+bsv, acc[i][3]+bsv);
        *(float4*)(dst + 4) = make_float4(acc[i][4]+bsv, acc[i][5]+bsv, acc[i][6]+bsv, acc[i][7]+bsv);
    }
}

// ---------------- q and k projections fused: M=64 (32 q rows + 32 k rows), N=128, K=256 ----------------
__global__ __launch_bounds__(256) void qk_gemm(const float* __restrict__ wq, const float* __restrict__ bq,
                                               const float* __restrict__ wk, const float* __restrict__ bk) {
    __shared__ float As[8][64];
    __shared__ float Bs[8][128];
    int tid = threadIdx.x, b = blockIdx.z;
    int p0 = blockIdx.x * 128;
    int arow = tid >> 2;
    int acol = (tid & 3) * 2;
    const float* ap = ((arow < 32) ? (wq + arow * CC) : (wk + (arow - 32) * CC)) + acol;
    int brow = tid >> 5, bcol = (tid & 31) * 4;
    const float* bp = g_out + (b * CC + brow) * NP + p0 + bcol;
    int ty = tid >> 4, tx = tid & 15;
    float acc[4][8];
    #pragma unroll
    for (int i = 0; i < 4; i++)
        #pragma unroll
        for (int j = 0; j < 8; j++) acc[i][j] = 0.f;

    for (int it = 0; it < CC / 8; ++it) {
        float2 av = *(const float2*)(ap + it * 8);
        float4 bv = *(const float4*)(bp + (size_t)it * 8 * NP);
        __syncthreads();
        As[acol + 0][arow] = av.x;
        As[acol + 1][arow] = av.y;
        *(float4*)&Bs[brow][bcol] = bv;
        __syncthreads();
        #pragma unroll
        for (int kk = 0; kk < 8; kk++) {
            float a[4], bvv[8];
            float4 t0 = *(const float4*)&As[kk][ty * 4];
            a[0]=t0.x; a[1]=t0.y; a[2]=t0.z; a[3]=t0.w;
            float4 u0 = *(const float4*)&Bs[kk][tx * 8];
            float4 u1 = *(const float4*)&Bs[kk][tx * 8 + 4];
            bvv[0]=u0.x; bvv[1]=u0.y; bvv[2]=u0.z; bvv[3]=u0.w;
            bvv[4]=u1.x; bvv[5]=u1.y; bvv[6]=u1.z; bvv[7]=u1.w;
            #pragma unroll
            for (int i = 0; i < 4; i++)
                #pragma unroll
                for (int j = 0; j < 8; j++)
                    acc[i][j] += a[i] * bvv[j];
        }
    }
    #pragma unroll
    for (int i = 0; i < 4; i++) {
        int row = ty * 4 + i;
        float bias = (row < 32) ? bq[row] : bk[row - 32];
        float* dst = ((row < 32) ? (g_q + (b * C8 + row) * NP)
                                 : (g_k + (b * C8 + row - 32) * NP)) + p0 + tx * 8;
        *(float4*)dst       = make_float4(acc[i][0]+bias, acc[i][1]+bias, acc[i][2]+bias, acc[i][3]+bias);
        *(float4*)(dst + 4) = make_float4(acc[i][4]+bias, acc[i][5]+bias, acc[i][6]+bias, acc[i][7]+bias);
    }
}

// ---------------- v projection: M=256, N=4096, K=256 ----------------
__global__ __launch_bounds__(256) void v_gemm(const float* __restrict__ wv, const float* __restrict__ bv) {
    __shared__ float As[8][128];
    __shared__ float Bs[8][128];
    int tid = threadIdx.x, b = blockIdx.z;
    int co0 = blockIdx.y * 128, p0 = blockIdx.x * 128;
    int arow = tid >> 1, acol = (tid & 1) * 4;
    const float* ap = wv + (co0 + arow) * CC + acol;
    int brow = tid >> 5, bcol = (tid & 31) * 4;
    const float* bp = g_out + (b * CC + brow) * NP + p0 + bcol;
    int ty = tid >> 4, tx = tid & 15;
    float acc[8][8];
    #pragma unroll
    for (int i = 0; i < 8; i++)
        #pragma unroll
        for (int j = 0; j < 8; j++) acc[i][j] = 0.f;

    for (int it = 0; it < CC / 8; ++it) {
        float4 av = *(const float4*)(ap + it * 8);
        float4 bvld = *(const float4*)(bp + (size_t)it * 8 * NP);
        __syncthreads();
        As[acol + 0][arow] = av.x;
        As[acol + 1][arow] = av.y;
        As[acol + 2][arow] = av.z;
        As[acol + 3][arow] = av.w;
        *(float4*)&Bs[brow][bcol] = bvld;
        __syncthreads();
        #pragma unroll
        for (int kk = 0; kk < 8; kk++) {
            float a[8], bb[8];
            float4 t0 = *(const float4*)&As[kk][ty * 8];
            float4 t1 = *(const float4*)&As[kk][ty * 8 + 4];
            a[0]=t0.x; a[1]=t0.y; a[2]=t0.z; a[3]=t0.w;
            a[4]=t1.x; a[5]=t1.y; a[6]=t1.z; a[7]=t1.w;
            float4 u0 = *(const float4*)&Bs[kk][tx * 8];
            float4 u1 = *(const float4*)&Bs[kk][tx * 8 + 4];
            bb[0]=u0.x; bb[1]=u0.y; bb[2]=u0.z; bb[3]=u0.w;
            bb[4]=u1.x; bb[5]=u1.y; bb[6]=u1.z; bb[7]=u1.w;
            #pragma unroll
            for (int i = 0; i < 8; i++)
                #pragma unroll
                for (int j = 0; j < 8; j++)
                    acc[i][j] += a[i] * bb[j];
        }
    }
    #pragma unroll
    for (int i = 0; i < 8; i++) {
        int co = co0 + ty * 8 + i;
        float bsv = bv[co];
        float* dst = g_v + ((b * CC + co) * NP) + p0 + tx * 8;
        *(float4*)dst       = make_float4(acc[i][0]+bsv, acc[i][1]+bsv, acc[i][2]+bsv, acc[i][3]+bsv);
        *(float4*)(dst + 4) = make_float4(acc[i][4]+bsv, acc[i][5]+bsv, acc[i][6]+bsv, acc[i][7]+bsv);
    }
}

// ---------------- energy[b,i,j] = sum_c q[b,c,i]*k[b,c,j], K=32 one shot ----------------
__global__ __launch_bounds__(256) void energy_kernel() {
    __shared__ float qs[32][128];
    __shared__ float ks[32][128];
    int tid = threadIdx.x, b = blockIdx.z;
    int i0 = blockIdx.y * 128, j0 = blockIdx.x * 128;
    #pragma unroll
    for (int s = 0; s < 4; s++) {
        int v = tid + s * 256;        // float4 slot 0..1023
        int c = v >> 5, col = (v & 31) * 4;
        *(float4*)&qs[c][col] = *(const float4*)(g_q + (b * C8 + c) * NP + i0 + col);
        *(float4*)&ks[c][col] = *(const float4*)(g_k + (b * C8 + c) * NP + j0 + col);
    }
    __syncthreads();
    int ty = tid >> 4, tx = tid & 15;
    float acc[8][8];
    #pragma unroll
    for (int i = 0; i < 8; i++)
        #pragma unroll
        for (int j = 0; j < 8; j++) acc[i][j] = 0.f;
    #pragma unroll
    for (int c = 0; c < 32; c++) {
        float a[8], bb[8];
        float4 t0 = *(const float4*)&qs[c][ty * 8];
        float4 t1 = *(const float4*)&qs[c][ty * 8 + 4];
        a[0]=t0.x; a[1]=t0.y; a[2]=t0.z; a[3]=t0.w;
        a[4]=t1.x; a[5]=t1.y; a[6]=t1.z; a[7]=t1.w;
        float4 u0 = *(const float4*)&ks[c][tx * 8];
        float4 u1 = *(const float4*)&ks[c][tx * 8 + 4];
        bb[0]=u0.x; bb[1]=u0.y; bb[2]=u0.z; bb[3]=u0.w;
        bb[4]=u1.x; bb[5]=u1.y; bb[6]=u1.z; bb[7]=u1.w;
        #pragma unroll
        for (int i = 0; i < 8; i++)
            #pragma unroll
            for (int j = 0; j < 8; j++)
                acc[i][j] += a[i] * bb[j];
    }
    #pragma unroll
    for (int i = 0; i < 8; i++) {
        float* dst = g_attn + ((size_t)b * NP + i0 + ty * 8 + i) * NP + j0 + tx * 8;
        *(float4*)dst       = make_float4(acc[i][0], acc[i][1], acc[i][2], acc[i][3]);
        *(float4*)(dst + 4) = make_float4(acc[i][4], acc[i][5], acc[i][6], acc[i][7]);
    }
}

// ---------------- row softmax over 4096, in place ----------------
__global__ __launch_bounds__(256) void softmax_kernel() {
    size_t row = blockIdx.x;
    float* ptr = g_attn + row * (size_t)NP;
    int tid = threadIdx.x;
    float vals[16];
    float m = -1e30f;
    #pragma unroll
    for (int s = 0; s < 16; s++) {
        vals[s] = ptr[tid + s * 256];
        m = fmaxf(m, vals[s]);
    }
    #pragma unroll
    for (int o = 16; o; o >>= 1) m = fmaxf(m, __shfl_xor_sync(0xffffffffu, m, o));
    __shared__ float shm[8], shs[8];
    int w = tid >> 5, l = tid & 31;
    if (l == 0) shm[w] = m;
    __syncthreads();
    m = fmaxf(fmaxf(fmaxf(shm[0], shm[1]), fmaxf(shm[2], shm[3])),
              fmaxf(fmaxf(shm[4], shm[5]), fmaxf(shm[6], shm[7])));
    float sum = 0.f;
    #pragma unroll
    for (int s = 0; s < 16; s++) {
        vals[s] = __expf(vals[s] - m);
        sum += vals[s];
    }
    #pragma unroll
    for (int o = 16; o; o >>= 1) sum += __shfl_xor_sync(0xffffffffu, sum, o);
    if (l == 0) shs[w] = sum;
    __syncthreads();
    sum = shs[0] + shs[1] + shs[2] + shs[3] + shs[4] + shs[5] + shs[6] + shs[7];
    float inv = 1.0f / sum;
    #pragma unroll
    for (int s = 0; s < 16; s++) ptr[tid + s * 256] = vals[s] * inv;
}

// ---------------- o[c,i] = sum_j v[c,j]*attn[i,j]; epilogue: dout = gamma*o + out ----------------
__global__ __launch_bounds__(256) void o_gemm(const float* __restrict__ gamma, float* __restrict__ dout) {
    __shared__ float As[8][128];
    __shared__ float Bs[8][128];
    int tid = threadIdx.x, b = blockIdx.z;
    int c0 = blockIdx.y * 128, i0 = blockIdx.x * 128;
    int arow = tid >> 1, acol = (tid & 1) * 4;
    const float* ap = g_v + (b * CC + c0 + arow) * NP + acol;
    int bi = tid >> 1, bk4 = (tid & 1) * 4;
    const float* bp = g_attn + ((size_t)b * NP + i0 + bi) * NP + bk4;
    int ty = tid >> 4, tx = tid & 15;
    float acc[8][8];
    #pragma unroll
    for (int i = 0; i < 8; i++)
        #pragma unroll
        for (int j = 0; j < 8; j++) acc[i][j] = 0.f;

    for (int it = 0; it < NP / 8; ++it) {
        float4 av = *(const float4*)(ap + it * 8);
        float4 bvld = *(const float4*)(bp + it * 8);
        __syncthreads();
        As[acol + 0][arow] = av.x;
        As[acol + 1][arow] = av.y;
        As[acol + 2][arow] = av.z;
        As[acol + 3][arow] = av.w;
        Bs[bk4 + 0][bi] = bvld.x;
        Bs[bk4 + 1][bi] = bvld.y;
        Bs[bk4 + 2][bi] = bvld.z;
        Bs[bk4 + 3][bi] = bvld.w;
        __syncthreads();
        #pragma unroll
        for (int kk = 0; kk < 8; kk++) {
            float a[8], bb[8];
            float4 t0 = *(const float4*)&As[kk][ty * 8];
            float4 t1 = *(const float4*)&As[kk][ty * 8 + 4];
            a[0]=t0.x; a[1]=t0.y; a[2]=t0.z; a[3]=t0.w;
            a[4]=t1.x; a[5]=t1.y; a[6]=t1.z; a[7]=t1.w;
            float4 u0 = *(const float4*)&Bs[kk][tx * 8];
            float4 u1 = *(const float4*)&Bs[kk][tx * 8 + 4];
            bb[0]=u0.x; bb[1]=u0.y; bb[2]=u0.z; bb[3]=u0.w;
            bb[4]=u1.x; bb[5]=u1.y; bb[6]=u1.z; bb[7]=u1.w;
            #pragma unroll
            for (int i = 0; i < 8; i++)
                #pragma unroll
                for (int j = 0; j < 8; j++)
                    acc[i][j] += a[i] * bb[j];
        }
    }
    float g = gamma[0];
    #pragma unroll
    for (int i = 0; i < 8; i++) {
        size_t base = (size_t)(b * CC + c0 + ty * 8 + i) * NP + i0 + tx * 8;
        const float* res = g_out + base;
        float* dst = dout + base;
        *(float4*)dst = make_float4(g * acc[i][0] + res[0], g * acc[i][1] + res[1],
                                    g * acc[i][2] + res[2], g * acc[i][3] + res[3]);
        *(float4*)(dst + 4) = make_float4(g * acc[i][4] + res[4], g * acc[i][5] + res[5],
                                          g * acc[i][6] + res[6], g * acc[i][7] + res[7]);
    }
}

// ---------------- launcher ----------------
extern "C" void kernel_launch(void* const* d_in, const int* in_sizes, int n_in,
                              void* d_out, int out_size) {
    const float* x     = (const float*)d_in[0];
    const float* w1    = (const float*)d_in[1];
    const float* b1    = (const float*)d_in[2];
    const float* w2    = (const float*)d_in[3];
    const float* b2    = (const float*)d_in[4];
    const float* wq    = (const float*)d_in[5];
    const float* bq    = (const float*)d_in[6];
    const float* wk    = (const float*)d_in[7];
    const float* bk    = (const float*)d_in[8];
    const float* wv    = (const float*)d_in[9];
    const float* bv    = (const float*)d_in[10];
    const float* gamma = (const float*)d_in[11];
    float* out = (float*)d_out;

    dim3 gconv(NP / 128, CC / 128, BB);   // (32,2,2)

    // conv block
    pad_kernel<<<BB * CC, 256>>>(x, 0);
    conv_gemm<<<gconv, 256>>>(w1, b1);
    stats_kernel<<<BB * CC, 256>>>();
    pad_kernel<<<BB * CC, 256>>>(nullptr, 1);      // instnorm + relu + pad
    conv_gemm<<<gconv, 256>>>(w2, b2);
    stats_kernel<<<BB * CC, 256>>>();
    norm_add_kernel<<<BB * CC * NP / 256, 256>>>(x);

    // attention
    qk_gemm<<<dim3(NP / 128, 1, BB), 256>>>(wq, bq, wk, bk);
    v_gemm<<<gconv, 256>>>(wv, bv);
    energy_kernel<<<dim3(NP / 128, NP / 128, BB), 256>>>();
    softmax_kernel<<<BB * NP, 256>>>();
    o_gemm<<<dim3(NP / 128, CC / 128, BB), 256>>>(gamma, out);
}

// round 2
// speedup vs baseline: 1.4113x; 1.4113x over previous
#include <cuda_runtime.h>
#include <math.h>
#include <stdint.h>

#define EPSV 1e-5f
#define BB 2
#define CC 256
#define C8 32
#define NP 4096          // 16*16*16 positions
#define PADN 5832        // 18*18*18
#define KCONV (CC*27)    // 6912

// ---------------- scratch ----------------
__device__ float g_pad[BB*CC*PADN];
__device__ float g_y[BB*CC*NP];
__device__ float g_out[BB*CC*NP];
__device__ float g_q[BB*C8*NP];
__device__ float g_k[BB*C8*NP];
__device__ float g_v[BB*CC*NP];
__device__ float g_attn[(size_t)BB*NP*NP];
__device__ float g_mean[BB*CC];
__device__ float g_rstd[BB*CC];

__constant__ int c_doff[27] = {
  -343,-342,-341,-325,-324,-323,-307,-306,-305,
   -19, -18, -17,  -1,   0,   1,  17,  18,  19,
   305, 306, 307, 323, 324, 325, 341, 342, 343};

// ---------------- tf32 helpers ----------------
__device__ __forceinline__ float tf32r(float x) {
    uint32_t u;
    asm("cvt.rna.tf32.f32 %0, %1;" : "=r"(u) : "f"(x));
    return __uint_as_float(u);
}

__device__ __forceinline__ void mma_tf32(float (&d)[4], const float4 &a, const float2 &b) {
    asm volatile(
        "mma.sync.aligned.m16n8k8.row.col.f32.tf32.tf32.f32 "
        "{%0,%1,%2,%3}, {%4,%5,%6,%7}, {%8,%9}, {%0,%1,%2,%3};\n"
        : "+f"(d[0]), "+f"(d[1]), "+f"(d[2]), "+f"(d[3])
        : "r"(__float_as_uint(a.x)), "r"(__float_as_uint(a.y)),
          "r"(__float_as_uint(a.z)), "r"(__float_as_uint(a.w)),
          "r"(__float_as_uint(b.x)), "r"(__float_as_uint(b.y)));
}

// ---------------- pad kernel ----------------
__global__ void pad_kernel(const float* __restrict__ x, int mode) {
    int bc = blockIdx.x;
    const float* src = (mode == 0) ? (x + bc * NP) : (g_y + bc * NP);
    float m = 0.f, r = 1.f;
    if (mode == 1) { m = g_mean[bc]; r = g_rstd[bc]; }
    float* dst = g_pad + bc * PADN;
    for (int i = threadIdx.x; i < PADN; i += blockDim.x) {
        int zp = i % 18; int t = i / 18; int yp = t % 18; int xp = t / 18;
        float v = 0.f;
        if (xp >= 1 && xp <= 16 && yp >= 1 && yp <= 16 && zp >= 1 && zp <= 16) {
            v = src[(xp - 1) * 256 + (yp - 1) * 16 + (zp - 1)];
            if (mode == 1) { v = (v - m) * r; v = v > 0.f ? v : 0.f; }
        }
        dst[i] = v;
    }
}

// ---------------- stats ----------------
__global__ void stats_kernel() {
    int bc = blockIdx.x;
    const float* src = g_y + bc * NP;
    float s = 0.f, ss = 0.f;
    for (int i = threadIdx.x; i < NP; i += 256) {
        float v = src[i]; s += v; ss += v * v;
    }
    #pragma unroll
    for (int o = 16; o; o >>= 1) {
        s  += __shfl_down_sync(0xffffffffu, s, o);
        ss += __shfl_down_sync(0xffffffffu, ss, o);
    }
    __shared__ float sh_s[8], sh_ss[8];
    int w = threadIdx.x >> 5, l = threadIdx.x & 31;
    if (l == 0) { sh_s[w] = s; sh_ss[w] = ss; }
    __syncthreads();
    if (threadIdx.x == 0) {
        float S = 0.f, SS = 0.f;
        #pragma unroll
        for (int i = 0; i < 8; i++) { S += sh_s[i]; SS += sh_ss[i]; }
        float m = S * (1.0f / NP);
        float var = SS * (1.0f / NP) - m * m;
        g_mean[bc] = m;
        g_rstd[bc] = rsqrtf(var + EPSV);
    }
}

// ---------------- out = x + instnorm(g_y) ----------------
__global__ void norm_add_kernel(const float* __restrict__ x) {
    int idx = blockIdx.x * 256 + threadIdx.x;
    int bc = idx >> 12;
    float m = g_mean[bc], r = g_rstd[bc];
    g_out[idx] = x[idx] + (g_y[idx] - m) * r;
}

// ============================================================================
// Tensor-core conv GEMM: g_y[b,co,p] = sum_k w[co,k]*g_pad[b,cin,p+off] + bias
// block tile 128(m=co) x 128(n=p), k-step 16, mma.m16n8k8.tf32
// smem staged in fragment-native layout: As[mtile][kblk][lane][4], Bs[nt][kb][lane][2]
// ============================================================================
__global__ __launch_bounds__(256) void conv_gemm_tc(const float* __restrict__ w,
                                                    const float* __restrict__ bias) {
    __shared__ float As[8][2][32][4];   // 8KB
    __shared__ float Bs[16][2][32][2];  // 8KB
    int tid = threadIdx.x, b = blockIdx.z;
    int co0 = blockIdx.y * 128, p0 = blockIdx.x * 128;
    const float* xb = g_pad + b * CC * PADN;

    // A loader: thread -> (row=tid>>1 in 0..127, half cg=tid&1 -> k cols cg*8..+7)
    int arow = tid >> 1, acg = tid & 1;
    const float* aptr = w + (size_t)(co0 + arow) * KCONV + acg * 8;
    int amt = arow >> 4, ar = arow & 15;
    int alb = (ar & 7) * 4;      // lane base
    int ajr = ar >> 3;           // j row bit

    // B loader: thread -> (k row kl=tid>>4 in 0..15, n group ng=tid&15 -> 8 n)
    int kl = tid >> 4, ng = tid & 15;
    int p = p0 + ng * 8;
    int pz = p & 15, py = (p >> 4) & 15, px = p >> 8;
    int pbase = (px + 1) * 324 + (py + 1) * 18 + (pz + 1);
    int bkblk = kl >> 3, bkc = kl & 7;
    int blb = bkc & 3, bj = bkc >> 2;
    int cin = 0, tap = kl;

    int wid = tid >> 5, lane = tid & 31;
    int wm = wid & 1, wn = wid >> 1;  // warp tile 64(m) x 32(n)

    float acc[4][4][4];
    #pragma unroll
    for (int i = 0; i < 4; i++)
        #pragma unroll
        for (int j = 0; j < 4; j++)
            #pragma unroll
            for (int k = 0; k < 4; k++) acc[i][j][k] = 0.f;

    for (int it = 0; it < KCONV / 16; ++it) {
        float4 a0 = *(const float4*)aptr;
        float4 a1 = *(const float4*)(aptr + 4);
        aptr += 16;
        const float* src = xb + cin * PADN + c_doff[tap] + pbase;
        float bv[8];
        #pragma unroll
        for (int j = 0; j < 8; j++) bv[j] = src[j];
        tap += 16; if (tap >= 27) { tap -= 27; cin++; }

        __syncthreads();
        {
            float av[8] = {a0.x, a0.y, a0.z, a0.w, a1.x, a1.y, a1.z, a1.w};
            #pragma unroll
            for (int cc = 0; cc < 8; cc++)
                As[amt][acg][alb + (cc & 3)][ajr + ((cc >> 2) << 1)] = tf32r(av[cc]);
            #pragma unroll
            for (int nn = 0; nn < 8; nn++)
                Bs[ng][bkblk][nn * 4 + blb][bj] = tf32r(bv[nn]);
        }
        __syncthreads();

        #pragma unroll
        for (int kb = 0; kb < 2; kb++) {
            float4 af[4]; float2 bf[4];
            #pragma unroll
            for (int mt = 0; mt < 4; mt++) af[mt] = *(const float4*)As[wm * 4 + mt][kb][lane];
            #pragma unroll
            for (int nt = 0; nt < 4; nt++) bf[nt] = *(const float2*)Bs[wn * 4 + nt][kb][lane];
            #pragma unroll
            for (int mt = 0; mt < 4; mt++)
                #pragma unroll
                for (int nt = 0; nt < 4; nt++)
                    mma_tf32(acc[mt][nt], af[mt], bf[nt]);
        }
    }

    int g = lane >> 2, tg = lane & 3;
    #pragma unroll
    for (int mt = 0; mt < 4; mt++) {
        int m = co0 + wm * 64 + mt * 16 + g;
        float bs0 = bias[m], bs1 = bias[m + 8];
        #pragma unroll
        for (int nt = 0; nt < 4; nt++) {
            int n = p0 + wn * 32 + nt * 8 + tg * 2;
            float* d0 = g_y + (size_t)(b * CC + m) * NP + n;
            *(float2*)d0 = make_float2(acc[mt][nt][0] + bs0, acc[mt][nt][1] + bs0);
            *(float2*)(d0 + 8 * NP) = make_float2(acc[mt][nt][2] + bs1, acc[mt][nt][3] + bs1);
        }
    }
}

// ============================================================================
// Tensor-core o GEMM: o[c,i] = sum_j v[c,j]*attn[i,j]; dout = gamma*o + out
// M=256(c), N=4096(i), K=4096(j)
// ============================================================================
__global__ __launch_bounds__(256) void o_gemm_tc(const float* __restrict__ gamma,
                                                 float* __restrict__ dout) {
    __shared__ float As[8][2][32][4];
    __shared__ float Bs[16][2][32][2];
    int tid = threadIdx.x, b = blockIdx.z;
    int c0 = blockIdx.y * 128, i0 = blockIdx.x * 128;

    int arow = tid >> 1, acg = tid & 1;
    const float* aptr = g_v + (size_t)(b * CC + c0 + arow) * NP + acg * 8;
    int amt = arow >> 4, ar = arow & 15;
    int alb = (ar & 7) * 4, ajr = ar >> 3;

    int bn = tid >> 1, bcg = tid & 1;
    const float* bptr = g_attn + ((size_t)b * NP + i0 + bn) * NP + bcg * 8;
    int bnt = bn >> 3, bnn = bn & 7;

    int wid = tid >> 5, lane = tid & 31;
    int wm = wid & 1, wn = wid >> 1;

    float acc[4][4][4];
    #pragma unroll
    for (int i = 0; i < 4; i++)
        #pragma unroll
        for (int j = 0; j < 4; j++)
            #pragma unroll
            for (int k = 0; k < 4; k++) acc[i][j][k] = 0.f;

    for (int it = 0; it < NP / 16; ++it) {
        float4 a0 = *(const float4*)aptr;
        float4 a1 = *(const float4*)(aptr + 4);
        aptr += 16;
        float4 b0 = *(const float4*)bptr;
        float4 b1 = *(const float4*)(bptr + 4);
        bptr += 16;

        __syncthreads();
        {
            float av[8] = {a0.x, a0.y, a0.z, a0.w, a1.x, a1.y, a1.z, a1.w};
            #pragma unroll
            for (int cc = 0; cc < 8; cc++)
                As[amt][acg][alb + (cc & 3)][ajr + ((cc >> 2) << 1)] = tf32r(av[cc]);
            float bvv[8] = {b0.x, b0.y, b0.z, b0.w, b1.x, b1.y, b1.z, b1.w};
            #pragma unroll
            for (int cc = 0; cc < 8; cc++)
                Bs[bnt][bcg][bnn * 4 + (cc & 3)][cc >> 2] = tf32r(bvv[cc]);
        }
        __syncthreads();

        #pragma unroll
        for (int kb = 0; kb < 2; kb++) {
            float4 af[4]; float2 bf[4];
            #pragma unroll
            for (int mt = 0; mt < 4; mt++) af[mt] = *(const float4*)As[wm * 4 + mt][kb][lane];
            #pragma unroll
            for (int nt = 0; nt < 4; nt++) bf[nt] = *(const float2*)Bs[wn * 4 + nt][kb][lane];
            #pragma unroll
            for (int mt = 0; mt < 4; mt++)
                #pragma unroll
                for (int nt = 0; nt < 4; nt++)
                    mma_tf32(acc[mt][nt], af[mt], bf[nt]);
        }
    }

    float gm = gamma[0];
    int g = lane >> 2, tg = lane & 3;
    #pragma unroll
    for (int mt = 0; mt < 4; mt++) {
        int m = c0 + wm * 64 + mt * 16 + g;
        #pragma unroll
        for (int nt = 0; nt < 4; nt++) {
            int n = i0 + wn * 32 + nt * 8 + tg * 2;
            size_t base0 = (size_t)(b * CC + m) * NP + n;
            size_t base1 = base0 + (size_t)8 * NP;
            const float* r0 = g_out + base0;
            const float* r1 = g_out + base1;
            *(float2*)(dout + base0) =
                make_float2(gm * acc[mt][nt][0] + r0[0], gm * acc[mt][nt][1] + r0[1]);
            *(float2*)(dout + base1) =
                make_float2(gm * acc[mt][nt][2] + r1[0], gm * acc[mt][nt][3] + r1[1]);
        }
    }
}

// ============================================================================
// Tensor-core energy: energy[b,i,j] = sum_c q[b,c,i]*k[b,c,j]  (K=32)
// ============================================================================
__global__ __launch_bounds__(256) void energy_tc() {
    __shared__ float As[8][2][32][4];
    __shared__ float Bs[16][2][32][2];
    int tid = threadIdx.x, b = blockIdx.z;
    int i0 = blockIdx.y * 128, j0 = blockIdx.x * 128;

    // loader: thread -> (k row cl=tid>>4 in 0..15, 8 consecutive i / j)
    int cl = tid >> 4, ig = tid & 15;
    int ckblk = cl >> 3, ckc = cl & 7;

    int wid = tid >> 5, lane = tid & 31;
    int wm = wid & 1, wn = wid >> 1;

    float acc[4][4][4];
    #pragma unroll
    for (int i = 0; i < 4; i++)
        #pragma unroll
        for (int j = 0; j < 4; j++)
            #pragma unroll
            for (int k = 0; k < 4; k++) acc[i][j][k] = 0.f;

    #pragma unroll
    for (int it = 0; it < 2; ++it) {
        int c = it * 16 + cl;
        const float* qsrc = g_q + (size_t)(b * C8 + c) * NP + i0 + ig * 8;
        const float* ksrc = g_k + (size_t)(b * C8 + c) * NP + j0 + ig * 8;
        float4 q0 = *(const float4*)qsrc, q1 = *(const float4*)(qsrc + 4);
        float4 k0 = *(const float4*)ksrc, k1 = *(const float4*)(ksrc + 4);

        __syncthreads();
        {
            float qv[8] = {q0.x, q0.y, q0.z, q0.w, q1.x, q1.y, q1.z, q1.w};
            #pragma unroll
            for (int ii = 0; ii < 8; ii++) {
                int r = ig * 8 + ii;
                int mtile = r >> 4, rr = r & 15;
                As[mtile][ckblk][(rr & 7) * 4 + (ckc & 3)][(rr >> 3) + ((ckc >> 2) << 1)] = tf32r(qv[ii]);
            }
            float kv[8] = {k0.x, k0.y, k0.z, k0.w, k1.x, k1.y, k1.z, k1.w};
            #pragma unroll
            for (int nn = 0; nn < 8; nn++)
                Bs[ig][ckblk][nn * 4 + (ckc & 3)][ckc >> 2] = tf32r(kv[nn]);
        }
        __syncthreads();

        #pragma unroll
        for (int kb = 0; kb < 2; kb++) {
            float4 af[4]; float2 bf[4];
            #pragma unroll
            for (int mt = 0; mt < 4; mt++) af[mt] = *(const float4*)As[wm * 4 + mt][kb][lane];
            #pragma unroll
            for (int nt = 0; nt < 4; nt++) bf[nt] = *(const float2*)Bs[wn * 4 + nt][kb][lane];
            #pragma unroll
            for (int mt = 0; mt < 4; mt++)
                #pragma unroll
                for (int nt = 0; nt < 4; nt++)
                    mma_tf32(acc[mt][nt], af[mt], bf[nt]);
        }
    }

    int g = lane >> 2, tg = lane & 3;
    #pragma unroll
    for (int mt = 0; mt < 4; mt++) {
        int m = i0 + wm * 64 + mt * 16 + g;
        #pragma unroll
        for (int nt = 0; nt < 4; nt++) {
            int n = j0 + wn * 32 + nt * 8 + tg * 2;
            float* d0 = g_attn + ((size_t)b * NP + m) * NP + n;
            *(float2*)d0 = make_float2(acc[mt][nt][0], acc[mt][nt][1]);
            *(float2*)(d0 + (size_t)8 * NP) = make_float2(acc[mt][nt][2], acc[mt][nt][3]);
        }
    }
}

// ---------------- q and k projections fused (FFMA, small) ----------------
__global__ __launch_bounds__(256) void qk_gemm(const float* __restrict__ wq, const float* __restrict__ bq,
                                               const float* __restrict__ wk, const float* __restrict__ bk) {
    __shared__ float As[8][64];
    __shared__ float Bs[8][128];
    int tid = threadIdx.x, b = blockIdx.z;
    int p0 = blockIdx.x * 128;
    int arow = tid >> 2;
    int acol = (tid & 3) * 2;
    const float* ap = ((arow < 32) ? (wq + arow * CC) : (wk + (arow - 32) * CC)) + acol;
    int brow = tid >> 5, bcol = (tid & 31) * 4;
    const float* bp = g_out + (b * CC + brow) * NP + p0 + bcol;
    int ty = tid >> 4, tx = tid & 15;
    float acc[4][8];
    #pragma unroll
    for (int i = 0; i < 4; i++)
        #pragma unroll
        for (int j = 0; j < 8; j++) acc[i][j] = 0.f;

    for (int it = 0; it < CC / 8; ++it) {
        float2 av = *(const float2*)(ap + it * 8);
        float4 bv = *(const float4*)(bp + (size_t)it * 8 * NP);
        __syncthreads();
        As[acol + 0][arow] = av.x;
        As[acol + 1][arow] = av.y;
        *(float4*)&Bs[brow][bcol] = bv;
        __syncthreads();
        #pragma unroll
        for (int kk = 0; kk < 8; kk++) {
            float a[4], bvv[8];
            float4 t0 = *(const float4*)&As[kk][ty * 4];
            a[0]=t0.x; a[1]=t0.y; a[2]=t0.z; a[3]=t0.w;
            float4 u0 = *(const float4*)&Bs[kk][tx * 8];
            float4 u1 = *(const float4*)&Bs[kk][tx * 8 + 4];
            bvv[0]=u0.x; bvv[1]=u0.y; bvv[2]=u0.z; bvv[3]=u0.w;
            bvv[4]=u1.x; bvv[5]=u1.y; bvv[6]=u1.z; bvv[7]=u1.w;
            #pragma unroll
            for (int i = 0; i < 4; i++)
                #pragma unroll
                for (int j = 0; j < 8; j++)
                    acc[i][j] += a[i] * bvv[j];
        }
    }
    #pragma unroll
    for (int i = 0; i < 4; i++) {
        int row = ty * 4 + i;
        float bias = (row < 32) ? bq[row] : bk[row - 32];
        float* dst = ((row < 32) ? (g_q + (b * C8 + row) * NP)
                                 : (g_k + (b * C8 + row - 32) * NP)) + p0 + tx * 8;
        *(float4*)dst       = make_float4(acc[i][0]+bias, acc[i][1]+bias, acc[i][2]+bias, acc[i][3]+bias);
        *(float4*)(dst + 4) = make_float4(acc[i][4]+bias, acc[i][5]+bias, acc[i][6]+bias, acc[i][7]+bias);
    }
}

// ---------------- v projection (FFMA, small) ----------------
__global__ __launch_bounds__(256) void v_gemm(const float* __restrict__ wv, const float* __restrict__ bv) {
    __shared__ float As[8][128];
    __shared__ float Bs[8][128];
    int tid = threadIdx.x, b = blockIdx.z;
    int co0 = blockIdx.y * 128, p0 = blockIdx.x * 128;
    int arow = tid >> 1, acol = (tid & 1) * 4;
    const float* ap = wv + (co0 + arow) * CC + acol;
    int brow = tid >> 5, bcol = (tid & 31) * 4;
    const float* bp = g_out + (b * CC + brow) * NP + p0 + bcol;
    int ty = tid >> 4, tx = tid & 15;
    float acc[8][8];
    #pragma unroll
    for (int i = 0; i < 8; i++)
        #pragma unroll
        for (int j = 0; j < 8; j++) acc[i][j] = 0.f;

    for (int it = 0; it < CC / 8; ++it) {
        float4 av = *(const float4*)(ap + it * 8);
        float4 bvld = *(const float4*)(bp + (size_t)it * 8 * NP);
        __syncthreads();
        As[acol + 0][arow] = av.x;
        As[acol + 1][arow] = av.y;
        As[acol + 2][arow] = av.z;
        As[acol + 3][arow] = av.w;
        *(float4*)&Bs[brow][bcol] = bvld;
        __syncthreads();
        #pragma unroll
        for (int kk = 0; kk < 8; kk++) {
            float a[8], bb[8];
            float4 t0 = *(const float4*)&As[kk][ty * 8];
            float4 t1 = *(const float4*)&As[kk][ty * 8 + 4];
            a[0]=t0.x; a[1]=t0.y; a[2]=t0.z; a[3]=t0.w;
            a[4]=t1.x; a[5]=t1.y; a[6]=t1.z; a[7]=t1.w;
            float4 u0 = *(const float4*)&Bs[kk][tx * 8];
            float4 u1 = *(const float4*)&Bs[kk][tx * 8 + 4];
            bb[0]=u0.x; bb[1]=u0.y; bb[2]=u0.z; bb[3]=u0.w;
            bb[4]=u1.x; bb[5]=u1.y; bb[6]=u1.z; bb[7]=u1.w;
            #pragma unroll
            for (int i = 0; i < 8; i++)
                #pragma unroll
                for (int j = 0; j < 8; j++)
                    acc[i][j] += a[i] * bb[j];
        }
    }
    #pragma unroll
    for (int i = 0; i < 8; i++) {
        int co = co0 + ty * 8 + i;
        float bsv = bv[co];
        float* dst = g_v + ((b * CC + co) * NP) + p0 + tx * 8;
        *(float4*)dst       = make_float4(acc[i][0]+bsv, acc[i][1]+bsv, acc[i][2]+bsv, acc[i][3]+bsv);
        *(float4*)(dst + 4) = make_float4(acc[i][4]+bsv, acc[i][5]+bsv, acc[i][6]+bsv, acc[i][7]+bsv);
    }
}

// ---------------- row softmax over 4096, in place ----------------
__global__ __launch_bounds__(256) void softmax_kernel() {
    size_t row = blockIdx.x;
    float* ptr = g_attn + row * (size_t)NP;
    int tid = threadIdx.x;
    float vals[16];
    float m = -1e30f;
    #pragma unroll
    for (int s = 0; s < 16; s++) {
        vals[s] = ptr[tid + s * 256];
        m = fmaxf(m, vals[s]);
    }
    #pragma unroll
    for (int o = 16; o; o >>= 1) m = fmaxf(m, __shfl_xor_sync(0xffffffffu, m, o));
    __shared__ float shm[8], shs[8];
    int w = tid >> 5, l = tid & 31;
    if (l == 0) shm[w] = m;
    __syncthreads();
    m = fmaxf(fmaxf(fmaxf(shm[0], shm[1]), fmaxf(shm[2], shm[3])),
              fmaxf(fmaxf(shm[4], shm[5]), fmaxf(shm[6], shm[7])));
    float sum = 0.f;
    #pragma unroll
    for (int s = 0; s < 16; s++) {
        vals[s] = __expf(vals[s] - m);
        sum += vals[s];
    }
    #pragma unroll
    for (int o = 16; o; o >>= 1) sum += __shfl_xor_sync(0xffffffffu, sum, o);
    if (l == 0) shs[w] = sum;
    __syncthreads();
    sum = shs[0] + shs[1] + shs[2] + shs[3] + shs[4] + shs[5] + shs[6] + shs[7];
    float inv = 1.0f / sum;
    #pragma unroll
    for (int s = 0; s < 16; s++) ptr[tid + s * 256] = vals[s] * inv;
}

// ---------------- launcher ----------------
extern "C" void kernel_launch(void* const* d_in, const int* in_sizes, int n_in,
                              void* d_out, int out_size) {
    const float* x     = (const float*)d_in[0];
    const float* w1    = (const float*)d_in[1];
    const float* b1    = (const float*)d_in[2];
    const float* w2    = (const float*)d_in[3];
    const float* b2    = (const float*)d_in[4];
    const float* wq    = (const float*)d_in[5];
    const float* bq    = (const float*)d_in[6];
    const float* wk    = (const float*)d_in[7];
    const float* bk    = (const float*)d_in[8];
    const float* wv    = (const float*)d_in[9];
    const float* bv    = (const float*)d_in[10];
    const float* gamma = (const float*)d_in[11];
    float* out = (float*)d_out;

    dim3 gconv(NP / 128, CC / 128, BB);   // (32,2,2)

    // conv block
    pad_kernel<<<BB * CC, 256>>>(x, 0);
    conv_gemm_tc<<<gconv, 256>>>(w1, b1);
    stats_kernel<<<BB * CC, 256>>>();
    pad_kernel<<<BB * CC, 256>>>(nullptr, 1);      // instnorm + relu + pad
    conv_gemm_tc<<<gconv, 256>>>(w2, b2);
    stats_kernel<<<BB * CC, 256>>>();
    norm_add_kernel<<<BB * CC * NP / 256, 256>>>(x);

    // attention
    qk_gemm<<<dim3(NP / 128, 1, BB), 256>>>(wq, bq, wk, bk);
    v_gemm<<<gconv, 256>>>(wv, bv);
    energy_tc<<<dim3(NP / 128, NP / 128, BB), 256>>>();
    softmax_kernel<<<BB * NP, 256>>>();
    o_gemm_tc<<<dim3(NP / 128, CC / 128, BB), 256>>>(gamma, out);
}

// round 5
// speedup vs baseline: 2.6328x; 1.8655x over previous
#include <cuda_runtime.h>
#include <math.h>
#include <stdint.h>

#define EPSV 1e-5f
#define BB 2
#define CC 256
#define C8 32
#define NP 4096          // 16*16*16 positions
#define PADN 5832        // 18*18*18
#define KCONV (CC*27)    // 6912

// ---------------- scratch ----------------
__device__ float g_pad[BB*CC*PADN];
__device__ float g_y[BB*CC*NP];
__device__ float g_out[BB*CC*NP];
__device__ float g_q[BB*C8*NP];
__device__ float g_k[BB*C8*NP];
__device__ float g_v[BB*CC*NP];
__device__ float g_attn[(size_t)BB*NP*NP];
__device__ float g_mean[BB*CC];
__device__ float g_rstd[BB*CC];
__device__ float g_wt[CC*KCONV];     // transposed conv weights: wt[co][tap*256+cin]

__constant__ int c_doff[27] = {
  -343,-342,-341,-325,-324,-323,-307,-306,-305,
   -19, -18, -17,  -1,   0,   1,  17,  18,  19,
   305, 306, 307, 323, 324, 325, 341, 342, 343};

// ---------------- tf32 helpers ----------------
__device__ __forceinline__ float tf32r(float x) {
    uint32_t u;
    asm("cvt.rna.tf32.f32 %0, %1;" : "=r"(u) : "f"(x));
    return __uint_as_float(u);
}
__device__ __forceinline__ void mma_tf32(float (&d)[4], const float4 &a, const float2 &b) {
    asm volatile(
        "mma.sync.aligned.m16n8k8.row.col.f32.tf32.tf32.f32 "
        "{%0,%1,%2,%3}, {%4,%5,%6,%7}, {%8,%9}, {%0,%1,%2,%3};\n"
        : "+f"(d[0]), "+f"(d[1]), "+f"(d[2]), "+f"(d[3])
        : "r"(__float_as_uint(a.x)), "r"(__float_as_uint(a.y)),
          "r"(__float_as_uint(a.z)), "r"(__float_as_uint(a.w)),
          "r"(__float_as_uint(b.x)), "r"(__float_as_uint(b.y)));
}

// ---------------- weight transpose: wt[co][tap*256+cin] = w[co][cin*27+tap] ----------------
__global__ __launch_bounds__(256) void wtrans_kernel(const float* __restrict__ w) {
    int co = blockIdx.x;
    int cin = threadIdx.x;
    const float* src = w + (size_t)co * KCONV + (size_t)cin * 27;
    float v[27];
    #pragma unroll
    for (int t = 0; t < 27; t++) v[t] = src[t];
    float* dst = g_wt + (size_t)co * KCONV + cin;
    #pragma unroll
    for (int t = 0; t < 27; t++) dst[t * 256] = v[t];
}

// ============================================================================
// Pipelined mma.sync tf32 GEMM, 128x128 tile, k-step 32, 2-stage smem.
// MODE 0 (CONV):  A=g_wt[co][k=(tap,cin)], B=im2col(g_pad), dst=g_y (+bias)
// MODE 1 (VPROJ): A=wv[co][c],             B=g_out[c][p],   dst=g_v (+bias)
// MODE 2 (OGEMM): A=g_v[c][j],             B=g_attn[i][j],  dst=gamma*acc+g_out
// ============================================================================
#define STG_FLOATS 8320
#define SMEM_DYN (2 * STG_FLOATS * 4)

template<int MODE, int KTOT>
__global__ __launch_bounds__(256, 1)
void tc_gemm(const float* __restrict__ Aext, const float* __restrict__ bias,
             const float* __restrict__ gamma, float* __restrict__ dout) {
    constexpr int NCH = KTOT / 32;
    extern __shared__ float sm[];
    const int tid = threadIdx.x, wid = tid >> 5, lane = tid & 31;
    const int bb = blockIdx.z;
    const int m0 = blockIdx.y * 128, n0 = blockIdx.x * 128;

    // ---- A loader: thread -> (mt=tid>>5, rowgroup=(tid>>2)&7, kb=tid&3) ----
    const int amt = tid >> 5;
    const int arg = (tid >> 2) & 7;
    const int akb = tid & 3;
    const float* aptr0;
    const float* aptr1;
    {
        int m = m0 + amt * 16 + arg;
        // NOTE: device-symbol bases must be resolved in device code, not passed
        // from host (host-side &g_wt is NOT a device pointer).
        const float* base = (MODE == 0) ? g_wt
                          : (MODE == 2) ? (g_v + (size_t)(bb * CC) * KTOT)
                          : Aext;
        aptr0 = base + (size_t)m * KTOT + akb * 8;
        aptr1 = base + (size_t)(m + 8) * KTOT + akb * 8;
    }

    // ---- B loader: thread -> (n=tid>>1, kb-half=(tid&1)*2) ----
    const int bn = tid >> 1;
    const int bkh = (tid & 1) * 2;
    int pofs = 0;
    const float* bbase = nullptr;
    if (MODE == 0) {
        int p = n0 + bn;
        int pz = p & 15, py = (p >> 4) & 15, px = p >> 8;
        pofs = (px + 1) * 324 + (py + 1) * 18 + (pz + 1);
        bbase = g_pad + (size_t)bb * CC * PADN;
    } else if (MODE == 1) {
        bbase = g_out + (size_t)bb * CC * NP + n0 + bn;
    } else {
        bbase = g_attn + ((size_t)bb * NP + n0 + bn) * NP + bkh * 8;
    }

    float ar0[8], ar1[8], br[16];

    #define LOAD_A(ch_) do { \
        *(float4*)(ar0)     = *(const float4*)(aptr0 + (size_t)(ch_) * 32); \
        *(float4*)(ar0 + 4) = *(const float4*)(aptr0 + (size_t)(ch_) * 32 + 4); \
        *(float4*)(ar1)     = *(const float4*)(aptr1 + (size_t)(ch_) * 32); \
        *(float4*)(ar1 + 4) = *(const float4*)(aptr1 + (size_t)(ch_) * 32 + 4); \
    } while (0)

    #define LOAD_B(ch_) do { \
        if (MODE == 2) { \
            *(float4*)(br)      = *(const float4*)(bbase + (size_t)(ch_) * 32); \
            *(float4*)(br + 4)  = *(const float4*)(bbase + (size_t)(ch_) * 32 + 4); \
            *(float4*)(br + 8)  = *(const float4*)(bbase + (size_t)(ch_) * 32 + 8); \
            *(float4*)(br + 12) = *(const float4*)(bbase + (size_t)(ch_) * 32 + 12); \
        } else if (MODE == 0) { \
            _Pragma("unroll") \
            for (int t = 0; t < 2; t++) { \
                _Pragma("unroll") \
                for (int c = 0; c < 8; c++) { \
                    int k = (ch_) * 32 + (bkh + t) * 8 + c; \
                    int tap = k >> 8, cin = k & 255; \
                    br[t * 8 + c] = bbase[cin * PADN + c_doff[tap] + pofs]; \
                } \
            } \
        } else { \
            _Pragma("unroll") \
            for (int t = 0; t < 2; t++) { \
                _Pragma("unroll") \
                for (int c = 0; c < 8; c++) { \
                    int k = (ch_) * 32 + (bkh + t) * 8 + c; \
                    br[t * 8 + c] = bbase[(size_t)k * NP]; \
                } \
            } \
        } \
    } while (0)

    #define STORE_AB(stg_) do { \
        float* As_ = sm + (stg_) * STG_FLOATS + amt * 512 + akb * 128 + arg * 16; \
        _Pragma("unroll") \
        for (int c = 0; c < 4; c++) { \
            *(float4*)(As_ + c * 4) = make_float4( \
                tf32r(ar0[c]), tf32r(ar1[c]), tf32r(ar0[c + 4]), tf32r(ar1[c + 4])); \
        } \
        float* Bs_ = sm + (stg_) * STG_FLOATS + 4096 + (bn >> 3) * 264 + (bn & 7) * 8; \
        _Pragma("unroll") \
        for (int t = 0; t < 2; t++) { \
            int kbb = bkh + t; \
            _Pragma("unroll") \
            for (int c = 0; c < 4; c++) { \
                *(float2*)(Bs_ + kbb * 64 + c * 2) = \
                    make_float2(tf32r(br[t * 8 + c]), tf32r(br[t * 8 + c + 4])); \
            } \
        } \
    } while (0)

    const int wm = wid & 1, wn = wid >> 1;
    float acc[4][4][4];
    #pragma unroll
    for (int i = 0; i < 4; i++)
        #pragma unroll
        for (int j = 0; j < 4; j++)
            #pragma unroll
            for (int k = 0; k < 4; k++) acc[i][j][k] = 0.f;

    // ---- prologue ----
    LOAD_A(0); LOAD_B(0);
    STORE_AB(0);
    LOAD_A(1); LOAD_B(1);
    __syncthreads();

    // ---- mainloop: 1 sync per iteration ----
    for (int ch = 0; ch < NCH; ch++) {
        int cur = ch & 1;
        if (ch + 1 < NCH) STORE_AB(cur ^ 1);
        if (ch + 2 < NCH) { LOAD_A(ch + 2); LOAD_B(ch + 2); }

        const float* As_ = sm + cur * STG_FLOATS;
        const float* Bs_ = As_ + 4096;
        #pragma unroll
        for (int kb = 0; kb < 4; kb++) {
            float4 af[4]; float2 bf[4];
            #pragma unroll
            for (int mt = 0; mt < 4; mt++)
                af[mt] = *(const float4*)(As_ + (wm * 4 + mt) * 512 + kb * 128 + lane * 4);
            #pragma unroll
            for (int nt = 0; nt < 4; nt++)
                bf[nt] = *(const float2*)(Bs_ + (wn * 4 + nt) * 264 + kb * 64 + lane * 2);
            #pragma unroll
            for (int mt = 0; mt < 4; mt++)
                #pragma unroll
                for (int nt = 0; nt < 4; nt++)
                    mma_tf32(acc[mt][nt], af[mt], bf[nt]);
        }
        __syncthreads();
    }

    #undef LOAD_A
    #undef LOAD_B
    #undef STORE_AB

    // ---- epilogue ----
    const int g = lane >> 2, tg = lane & 3;
    float gm = (MODE == 2) ? gamma[0] : 0.f;
    #pragma unroll
    for (int mt = 0; mt < 4; mt++) {
        int m = m0 + wm * 64 + mt * 16 + g;
        float bs0 = 0.f, bs1 = 0.f;
        if (MODE == 0 || MODE == 1) { bs0 = bias[m]; bs1 = bias[m + 8]; }
        #pragma unroll
        for (int nt = 0; nt < 4; nt++) {
            int n = n0 + wn * 32 + nt * 8 + tg * 2;
            size_t base0 = (size_t)(bb * CC + m) * NP + n;
            size_t base1 = base0 + (size_t)8 * NP;
            if (MODE == 0) {
                *(float2*)(g_y + base0) = make_float2(acc[mt][nt][0] + bs0, acc[mt][nt][1] + bs0);
                *(float2*)(g_y + base1) = make_float2(acc[mt][nt][2] + bs1, acc[mt][nt][3] + bs1);
            } else if (MODE == 1) {
                *(float2*)(g_v + base0) = make_float2(acc[mt][nt][0] + bs0, acc[mt][nt][1] + bs0);
                *(float2*)(g_v + base1) = make_float2(acc[mt][nt][2] + bs1, acc[mt][nt][3] + bs1);
            } else {
                const float* r0 = g_out + base0;
                const float* r1 = g_out + base1;
                *(float2*)(dout + base0) =
                    make_float2(gm * acc[mt][nt][0] + r0[0], gm * acc[mt][nt][1] + r0[1]);
                *(float2*)(dout + base1) =
                    make_float2(gm * acc[mt][nt][2] + r1[0], gm * acc[mt][nt][3] + r1[1]);
            }
        }
    }
}

// ---------------- pad kernel ----------------
__global__ void pad_kernel(const float* __restrict__ x, int mode) {
    int bc = blockIdx.x;
    const float* src = (mode == 0) ? (x + bc * NP) : (g_y + bc * NP);
    float m = 0.f, r = 1.f;
    if (mode == 1) { m = g_mean[bc]; r = g_rstd[bc]; }
    float* dst = g_pad + bc * PADN;
    for (int i = threadIdx.x; i < PADN; i += blockDim.x) {
        int zp = i % 18; int t = i / 18; int yp = t % 18; int xp = t / 18;
        float v = 0.f;
        if (xp >= 1 && xp <= 16 && yp >= 1 && yp <= 16 && zp >= 1 && zp <= 16) {
            v = src[(xp - 1) * 256 + (yp - 1) * 16 + (zp - 1)];
            if (mode == 1) { v = (v - m) * r; v = v > 0.f ? v : 0.f; }
        }
        dst[i] = v;
    }
}

// ---------------- stats ----------------
__global__ void stats_kernel() {
    int bc = blockIdx.x;
    const float* src = g_y + bc * NP;
    float s = 0.f, ss = 0.f;
    for (int i = threadIdx.x; i < NP; i += 256) {
        float v = src[i]; s += v; ss += v * v;
    }
    #pragma unroll
    for (int o = 16; o; o >>= 1) {
        s  += __shfl_down_sync(0xffffffffu, s, o);
        ss += __shfl_down_sync(0xffffffffu, ss, o);
    }
    __shared__ float sh_s[8], sh_ss[8];
    int w = threadIdx.x >> 5, l = threadIdx.x & 31;
    if (l == 0) { sh_s[w] = s; sh_ss[w] = ss; }
    __syncthreads();
    if (threadIdx.x == 0) {
        float S = 0.f, SS = 0.f;
        #pragma unroll
        for (int i = 0; i < 8; i++) { S += sh_s[i]; SS += sh_ss[i]; }
        float m = S * (1.0f / NP);
        float var = SS * (1.0f / NP) - m * m;
        g_mean[bc] = m;
        g_rstd[bc] = rsqrtf(var + EPSV);
    }
}

// ---------------- out = x + instnorm(g_y) ----------------
__global__ void norm_add_kernel(const float* __restrict__ x) {
    int idx = blockIdx.x * 256 + threadIdx.x;
    int bc = idx >> 12;
    float m = g_mean[bc], r = g_rstd[bc];
    g_out[idx] = x[idx] + (g_y[idx] - m) * r;
}

// ---------------- energy: energy[b,i,j] = sum_c q[b,c,i]*k[b,c,j], K=32 ----------------
__global__ __launch_bounds__(256) void energy_tc() {
    __shared__ float As[8][2][32][4];
    __shared__ float Bs[16][2][32][2];
    int tid = threadIdx.x, b = blockIdx.z;
    int i0 = blockIdx.y * 128, j0 = blockIdx.x * 128;

    int cl = tid >> 4, ig = tid & 15;
    int ckblk = cl >> 3, ckc = cl & 7;

    int wid = tid >> 5, lane = tid & 31;
    int wm = wid & 1, wn = wid >> 1;

    float acc[4][4][4];
    #pragma unroll
    for (int i = 0; i < 4; i++)
        #pragma unroll
        for (int j = 0; j < 4; j++)
            #pragma unroll
            for (int k = 0; k < 4; k++) acc[i][j][k] = 0.f;

    #pragma unroll
    for (int it = 0; it < 2; ++it) {
        int c = it * 16 + cl;
        const float* qsrc = g_q + (size_t)(b * C8 + c) * NP + i0 + ig * 8;
        const float* ksrc = g_k + (size_t)(b * C8 + c) * NP + j0 + ig * 8;
        float4 q0 = *(const float4*)qsrc, q1 = *(const float4*)(qsrc + 4);
        float4 k0 = *(const float4*)ksrc, k1 = *(const float4*)(ksrc + 4);

        __syncthreads();
        {
            float qv[8] = {q0.x, q0.y, q0.z, q0.w, q1.x, q1.y, q1.z, q1.w};
            #pragma unroll
            for (int ii = 0; ii < 8; ii++) {
                int r = ig * 8 + ii;
                int mtile = r >> 4, rr = r & 15;
                As[mtile][ckblk][(rr & 7) * 4 + (ckc & 3)][(rr >> 3) + ((ckc >> 2) << 1)] = tf32r(qv[ii]);
            }
            float kv[8] = {k0.x, k0.y, k0.z, k0.w, k1.x, k1.y, k1.z, k1.w};
            #pragma unroll
            for (int nn = 0; nn < 8; nn++)
                Bs[ig][ckblk][nn * 4 + (ckc & 3)][ckc >> 2] = tf32r(kv[nn]);
        }
        __syncthreads();

        #pragma unroll
        for (int kb = 0; kb < 2; kb++) {
            float4 af[4]; float2 bf[4];
            #pragma unroll
            for (int mt = 0; mt < 4; mt++) af[mt] = *(const float4*)As[wm * 4 + mt][kb][lane];
            #pragma unroll
            for (int nt = 0; nt < 4; nt++) bf[nt] = *(const float2*)Bs[wn * 4 + nt][kb][lane];
            #pragma unroll
            for (int mt = 0; mt < 4; mt++)
                #pragma unroll
                for (int nt = 0; nt < 4; nt++)
                    mma_tf32(acc[mt][nt], af[mt], bf[nt]);
        }
    }

    int g = lane >> 2, tg = lane & 3;
    #pragma unroll
    for (int mt = 0; mt < 4; mt++) {
        int m = i0 + wm * 64 + mt * 16 + g;
        #pragma unroll
        for (int nt = 0; nt < 4; nt++) {
            int n = j0 + wn * 32 + nt * 8 + tg * 2;
            float* d0 = g_attn + ((size_t)b * NP + m) * NP + n;
            *(float2*)d0 = make_float2(acc[mt][nt][0], acc[mt][nt][1]);
            *(float2*)(d0 + (size_t)8 * NP) = make_float2(acc[mt][nt][2], acc[mt][nt][3]);
        }
    }
}

// ---------------- q and k projections fused (FFMA, small) ----------------
__global__ __launch_bounds__(256) void qk_gemm(const float* __restrict__ wq, const float* __restrict__ bq,
                                               const float* __restrict__ wk, const float* __restrict__ bk) {
    __shared__ float As[8][64];
    __shared__ float Bs[8][128];
    int tid = threadIdx.x, b = blockIdx.z;
    int p0 = blockIdx.x * 128;
    int arow = tid >> 2;
    int acol = (tid & 3) * 2;
    const float* ap = ((arow < 32) ? (wq + arow * CC) : (wk + (arow - 32) * CC)) + acol;
    int brow = tid >> 5, bcol = (tid & 31) * 4;
    const float* bp = g_out + (b * CC + brow) * NP + p0 + bcol;
    int ty = tid >> 4, tx = tid & 15;
    float acc[4][8];
    #pragma unroll
    for (int i = 0; i < 4; i++)
        #pragma unroll
        for (int j = 0; j < 8; j++) acc[i][j] = 0.f;

    for (int it = 0; it < CC / 8; ++it) {
        float2 av = *(const float2*)(ap + it * 8);
        float4 bv = *(const float4*)(bp + (size_t)it * 8 * NP);
        __syncthreads();
        As[acol + 0][arow] = av.x;
        As[acol + 1][arow] = av.y;
        *(float4*)&Bs[brow][bcol] = bv;
        __syncthreads();
        #pragma unroll
        for (int kk = 0; kk < 8; kk++) {
            float a[4], bvv[8];
            float4 t0 = *(const float4*)&As[kk][ty * 4];
            a[0]=t0.x; a[1]=t0.y; a[2]=t0.z; a[3]=t0.w;
            float4 u0 = *(const float4*)&Bs[kk][tx * 8];
            float4 u1 = *(const float4*)&Bs[kk][tx * 8 + 4];
            bvv[0]=u0.x; bvv[1]=u0.y; bvv[2]=u0.z; bvv[3]=u0.w;
            bvv[4]=u1.x; bvv[5]=u1.y; bvv[6]=u1.z; bvv[7]=u1.w;
            #pragma unroll
            for (int i = 0; i < 4; i++)
                #pragma unroll
                for (int j = 0; j < 8; j++)
                    acc[i][j] += a[i] * bvv[j];
        }
    }
    #pragma unroll
    for (int i = 0; i < 4; i++) {
        int row = ty * 4 + i;
        float bias = (row < 32) ? bq[row] : bk[row - 32];
        float* dst = ((row < 32) ? (g_q + (b * C8 + row) * NP)
                                 : (g_k + (b * C8 + row - 32) * NP)) + p0 + tx * 8;
        *(float4*)dst       = make_float4(acc[i][0]+bias, acc[i][1]+bias, acc[i][2]+bias, acc[i][3]+bias);
        *(float4*)(dst + 4) = make_float4(acc[i][4]+bias, acc[i][5]+bias, acc[i][6]+bias, acc[i][7]+bias);
    }
}

// ---------------- row softmax over 4096, in place ----------------
__global__ __launch_bounds__(256) void softmax_kernel() {
    size_t row = blockIdx.x;
    float* ptr = g_attn + row * (size_t)NP;
    int tid = threadIdx.x;
    float vals[16];
    float m = -1e30f;
    #pragma unroll
    for (int s = 0; s < 16; s++) {
        vals[s] = ptr[tid + s * 256];
        m = fmaxf(m, vals[s]);
    }
    #pragma unroll
    for (int o = 16; o; o >>= 1) m = fmaxf(m, __shfl_xor_sync(0xffffffffu, m, o));
    __shared__ float shm[8], shs[8];
    int w = tid >> 5, l = tid & 31;
    if (l == 0) shm[w] = m;
    __syncthreads();
    m = fmaxf(fmaxf(fmaxf(shm[0], shm[1]), fmaxf(shm[2], shm[3])),
              fmaxf(fmaxf(shm[4], shm[5]), fmaxf(shm[6], shm[7])));
    float sum = 0.f;
    #pragma unroll
    for (int s = 0; s < 16; s++) {
        vals[s] = __expf(vals[s] - m);
        sum += vals[s];
    }
    #pragma unroll
    for (int o = 16; o; o >>= 1) sum += __shfl_xor_sync(0xffffffffu, sum, o);
    if (l == 0) shs[w] = sum;
    __syncthreads();
    sum = shs[0] + shs[1] + shs[2] + shs[3] + shs[4] + shs[5] + shs[6] + shs[7];
    float inv = 1.0f / sum;
    #pragma unroll
    for (int s = 0; s < 16; s++) ptr[tid + s * 256] = vals[s] * inv;
}

// ---------------- launcher ----------------
extern "C" void kernel_launch(void* const* d_in, const int* in_sizes, int n_in,
                              void* d_out, int out_size) {
    const float* x     = (const float*)d_in[0];
    const float* w1    = (const float*)d_in[1];
    const float* b1    = (const float*)d_in[2];
    const float* w2    = (const float*)d_in[3];
    const float* b2    = (const float*)d_in[4];
    const float* wq    = (const float*)d_in[5];
    const float* bq    = (const float*)d_in[6];
    const float* wk    = (const float*)d_in[7];
    const float* bk    = (const float*)d_in[8];
    const float* wv    = (const float*)d_in[9];
    const float* bv    = (const float*)d_in[10];
    const float* gamma = (const float*)d_in[11];
    float* out = (float*)d_out;

    cudaFuncSetAttribute(tc_gemm<0, KCONV>, cudaFuncAttributeMaxDynamicSharedMemorySize, SMEM_DYN);
    cudaFuncSetAttribute(tc_gemm<1, CC>,    cudaFuncAttributeMaxDynamicSharedMemorySize, SMEM_DYN);
    cudaFuncSetAttribute(tc_gemm<2, NP>,    cudaFuncAttributeMaxDynamicSharedMemorySize, SMEM_DYN);

    dim3 g128(NP / 128, CC / 128, BB);   // (32,2,2)

    // conv block  (A base for MODE 0 resolved in-kernel to g_wt)
    pad_kernel<<<BB * CC, 256>>>(x, 0);
    wtrans_kernel<<<CC, 256>>>(w1);
    tc_gemm<0, KCONV><<<g128, 256, SMEM_DYN>>>(nullptr, b1, nullptr, nullptr);
    stats_kernel<<<BB * CC, 256>>>();
    pad_kernel<<<BB * CC, 256>>>(nullptr, 1);      // instnorm + relu + pad
    wtrans_kernel<<<CC, 256>>>(w2);
    tc_gemm<0, KCONV><<<g128, 256, SMEM_DYN>>>(nullptr, b2, nullptr, nullptr);
    stats_kernel<<<BB * CC, 256>>>();
    norm_add_kernel<<<BB * CC * NP / 256, 256>>>(x);

    // attention
    qk_gemm<<<dim3(NP / 128, 1, BB), 256>>>(wq, bq, wk, bk);
    tc_gemm<1, CC><<<g128, 256, SMEM_DYN>>>(wv, bv, nullptr, nullptr);
    energy_tc<<<dim3(NP / 128, NP / 128, BB), 256>>>();
    softmax_kernel<<<BB * NP, 256>>>();
    tc_gemm<2, NP><<<g128, 256, SMEM_DYN>>>(nullptr, nullptr, gamma, out);
}